// round 10
// baseline (speedup 1.0000x reference)
#include <cuda_runtime.h>
#include <cstdint>

// out[t,:] = 1 / where(dmat[row(t),:]==0, BIG, dmat[row(t),:])
//   row(t) = venueid2coor[inputs_poi[t]]
// Dedup gather: per-row token lists; one CTA per (row, half-row segment);
// each unique row read from DRAM exactly once; fan out writes.
// R10: init+detect+build fused into one prep kernel (last-block pattern).

#define N_POI    10000
#define V_SIZE   20000
#define N_TOK    6400
#define MAX_BATCH 64

#define SEGMENTS 2
#define SEG_VEC  1250        // float4 per segment (2500 total per row)
#define FULL_IT  4           // 4*256 = 1024 vectors
#define TAIL     226         // 1250 - 1024

#define PREP_BLOCKS 20
#define PREP_THREADS 512     // 20*512 = 10240 >= N_POI

__device__ int g_head[N_POI];
__device__ int g_next[N_TOK];
__device__ int g_poi_is64;
__device__ int g_v2c_is64;
__device__ int g_done;       // zero-initialized; reset to 0 by last block each call

// Fused: clear head[], detect dtypes, then the LAST block to finish builds
// the per-row token lists. Deterministic: g_done returns to 0 every call.
__global__ void __launch_bounds__(PREP_THREADS) prep_kernel(
    const void* __restrict__ venueid2coor,
    const void* __restrict__ inputs_poi,
    int n_tok)
{
    const int gid = blockIdx.x * PREP_THREADS + threadIdx.x;

    // Phase A: init head[] and dtype detection.
    if (gid < N_POI) g_head[gid] = -1;
    if (gid == 0) {
        const unsigned int* poi = (const unsigned int*)inputs_poi;
        const unsigned int* v2c = (const unsigned int*)venueid2coor;
        int poi64 = 1, v2c64 = 1;
        #pragma unroll
        for (int k = 1; k < 32; k += 2) {      // LE int64 of small values -> odd words 0
            if (poi[k] != 0u) poi64 = 0;
            if (v2c[k] != 0u) v2c64 = 0;
        }
        g_poi_is64 = poi64;
        g_v2c_is64 = v2c64;
    }

    // Phase B: last block to arrive builds the lists.
    __syncthreads();
    __shared__ int s_last;
    if (threadIdx.x == 0) {
        __threadfence();
        s_last = (atomicAdd(&g_done, 1) == PREP_BLOCKS - 1);
    }
    __syncthreads();
    if (!s_last) return;
    __threadfence();                           // acquire prior blocks' writes

    const int poi64 = g_poi_is64;
    const int v2c64 = g_v2c_is64;

    for (int t = threadIdx.x; t < n_tok; t += PREP_THREADS) {
        long long vid = poi64 ? ((const long long*)inputs_poi)[t]
                              : (long long)((const int*)inputs_poi)[t];
        if (vid < 0) vid = 0;
        if (vid >= V_SIZE) vid = V_SIZE - 1;

        long long row = v2c64 ? ((const long long*)venueid2coor)[vid]
                              : (long long)((const int*)venueid2coor)[vid];
        if (row < 0) row = 0;
        if (row >= N_POI) row = N_POI - 1;

        g_next[t] = atomicExch(&g_head[(int)row], t);
    }

    if (threadIdx.x == 0) g_done = 0;          // reset for next graph replay
}

__device__ __forceinline__ float4 xform(float4 v)
{
    const float BIG = 9999999.99f;
    float4 r;
    r.x = __frcp_rn(v.x == 0.0f ? BIG : v.x);
    r.y = __frcp_rn(v.y == 0.0f ? BIG : v.y);
    r.z = __frcp_rn(v.z == 0.0f ? BIG : v.z);
    r.w = __frcp_rn(v.w == 0.0f ? BIG : v.w);
    return r;
}

// grid = (N_POI, SEGMENTS), block = 256.
__global__ void __launch_bounds__(256) fanout_kernel(
    const float* __restrict__ dmat,
    float*       __restrict__ out)
{
    const int row = blockIdx.x;
    int start = g_head[row];                 // uniform -> broadcast
    if (start < 0) return;

    const int tid = threadIdx.x;
    const int segbase = blockIdx.y * SEG_VEC;

    const float4* __restrict__ src =
        reinterpret_cast<const float4*>(dmat + (size_t)row * N_POI) + segbase;

    __shared__ float4* s_dst[MAX_BATCH];
    __shared__ int s_n;
    __shared__ int s_next;

    while (start >= 0) {
        if (tid == 0) {
            int n = 0, t = start;
            while (t >= 0 && n < MAX_BATCH) {
                s_dst[n++] = reinterpret_cast<float4*>(out + (size_t)t * N_POI) + segbase;
                t = g_next[t];
            }
            s_n = n;
            s_next = t;
        }
        __syncthreads();
        const int n = s_n;

        if (n == 1) {
            float4* __restrict__ dst = s_dst[0];
            float4 v[FULL_IT];
            #pragma unroll
            for (int k = 0; k < FULL_IT; k++)          // 4 independent loads in flight
                v[k] = __ldcs(&src[tid + k * 256]);
            #pragma unroll
            for (int k = 0; k < FULL_IT; k++)
                __stcs(&dst[tid + k * 256], xform(v[k]));
            if (tid < TAIL) {
                float4 t4 = __ldcs(&src[FULL_IT * 256 + tid]);
                __stcs(&dst[FULL_IT * 256 + tid], xform(t4));
            }
        } else {
            float4 r[FULL_IT];
            #pragma unroll
            for (int k = 0; k < FULL_IT; k++)
                r[k] = __ldcs(&src[tid + k * 256]);
            #pragma unroll
            for (int k = 0; k < FULL_IT; k++)
                r[k] = xform(r[k]);
            float4 rt;
            if (tid < TAIL)
                rt = xform(__ldcs(&src[FULL_IT * 256 + tid]));
            for (int j = 0; j < n; j++) {
                float4* __restrict__ dst = s_dst[j];
                #pragma unroll
                for (int k = 0; k < FULL_IT; k++)
                    __stcs(&dst[tid + k * 256], r[k]);
                if (tid < TAIL)
                    __stcs(&dst[FULL_IT * 256 + tid], rt);
            }
        }
        start = s_next;
        __syncthreads();
    }
}

extern "C" void kernel_launch(void* const* d_in, const int* in_sizes, int n_in,
                              void* d_out, int out_size)
{
    const void*  venueid2coor = d_in[0];
    const void*  inputs_poi   = d_in[1];
    const float* dmat         = (const float*)d_in[2];
    float*       out          = (float*)d_out;

    int n_tok = in_sizes[1];
    if (n_tok > N_TOK) n_tok = N_TOK;

    prep_kernel<<<PREP_BLOCKS, PREP_THREADS>>>(venueid2coor, inputs_poi, n_tok);

    dim3 grid(N_POI, SEGMENTS);
    fanout_kernel<<<grid, 256>>>(dmat, out);
}